// round 3
// baseline (speedup 1.0000x reference)
#include <cuda_runtime.h>

#define ESP      1e-12f
#define C_DIM    8192
#define THREADS  256
#define GRID     592            // 148 SMs x 4 blocks: exactly one wave
#define WPB      (THREADS / 32) // warps per block

__device__ double        g_accum;   // zero-init; reset by finalizer each run
__device__ unsigned int  g_ticket;  // zero-init; reset by finalizer each run

__device__ __forceinline__ float fsqrt_approx(float x) {
    float r;
    asm("sqrt.approx.f32 %0, %1;" : "=f"(r) : "f"(x));
    return r;
}

__global__ void __launch_bounds__(THREADS, 4) mfl_fused_kernel(
    const float* __restrict__ p,
    const float* __restrict__ g,
    float* __restrict__ out,
    int n_rows)
{
    const int lane    = threadIdx.x & 31;
    const int gwarp   = blockIdx.x * WPB + (threadIdx.x >> 5);
    const int n_warps = gridDim.x * WPB;

    double acc = 0.0;   // lane 0's running sum of row losses

    for (int row = gwarp; row < n_rows; row += n_warps) {
        const float4* __restrict__ p4 =
            reinterpret_cast<const float4*>(p + (size_t)row * C_DIM);
        const float4* __restrict__ g4 =
            reinterpret_cast<const float4*>(g + (size_t)row * C_DIM);

        float sum = 0.0f;
        int   cnt = 0;

        // 2048 float4 per row / 32 lanes = 64 per lane.
        // unroll 4 -> 8 LDG.128 in flight per warp, ~regs stay <= 64.
        #pragma unroll 4
        for (int i = 0; i < 64; i++) {
            float4 pv = __ldcs(&p4[lane + i * 32]);
            float4 gv = __ldcs(&g4[lane + i * 32]);

            #pragma unroll
            for (int k = 0; k < 4; k++) {
                float pe = (&pv.x)[k];
                float ge = (&gv.x)[k];
                float a = fmaf(pe, ge, ESP);
                float b = fmaf(1.0f - pe, 1.0f - ge, ESP);
                float l = 1.0f - (fsqrt_approx(a) + fsqrt_approx(b));
                bool nz = (ge != 0.0f);
                sum += nz ? l : 0.0f;
                cnt += nz ? 1 : 0;
            }
        }

        // Warp reduction (lane 0 ends with row totals)
        #pragma unroll
        for (int o = 16; o > 0; o >>= 1) {
            sum += __shfl_down_sync(0xffffffffu, sum, o);
            cnt += __shfl_down_sync(0xffffffffu, cnt, o);
        }

        if (lane == 0)
            acc += (cnt > 0) ? (double)(sum / (float)cnt) : 0.0;
    }

    if (lane == 0) {
        atomicAdd(&g_accum, acc);
        __threadfence();
        unsigned int t = atomicAdd(&g_ticket, 1u);
        if (t == (unsigned int)(n_warps - 1)) {
            // Last warp: read-and-reset accumulator + ticket atomically so
            // every graph replay starts from zeroed state (matches the
            // zero-initialized first call), then emit the result.
            unsigned long long bits =
                atomicExch((unsigned long long*)&g_accum, 0ull);
            atomicExch(&g_ticket, 0u);
            double total = __longlong_as_double((long long)bits);
            out[0] = (float)(total / (double)n_rows);
        }
    }
}

extern "C" void kernel_launch(void* const* d_in, const int* in_sizes, int n_in,
                              void* d_out, int out_size) {
    const float* p = (const float*)d_in[0];
    const float* g = (const float*)d_in[1];
    float* out = (float*)d_out;

    const int total = in_sizes[0];
    const int n_rows = total / C_DIM;   // 16384

    mfl_fused_kernel<<<GRID, THREADS>>>(p, g, out, n_rows);
}

// round 4
// speedup vs baseline: 1.0976x; 1.0976x over previous
#include <cuda_runtime.h>

#define ESP      1e-12f
#define C_DIM    8192
#define THREADS  256
#define ROWS_PER_BLOCK 2
#define GROUP    128            // threads cooperating on one row

__device__ double        g_accum;   // zero-init; reset by finalizer each run
__device__ unsigned int  g_ticket;  // zero-init; reset by finalizer each run

__device__ __forceinline__ float fsqrt_approx(float x) {
    float r;
    asm("sqrt.approx.f32 %0, %1;" : "=f"(r) : "f"(x));
    return r;
}

__global__ void __launch_bounds__(THREADS, 4) mfl_fused_kernel(
    const float* __restrict__ p,
    const float* __restrict__ g,
    float* __restrict__ out,
    int n_rows)
{
    const int tid   = threadIdx.x;
    const int half  = tid / GROUP;           // 0 or 1: which row this thread works
    const int gtid  = tid % GROUP;           // lane within the 128-thread group
    const int row   = blockIdx.x * ROWS_PER_BLOCK + half;

    const float4* __restrict__ p4 =
        reinterpret_cast<const float4*>(p + (size_t)row * C_DIM);
    const float4* __restrict__ g4 =
        reinterpret_cast<const float4*>(g + (size_t)row * C_DIM);

    float sum = 0.0f;
    int   cnt = 0;

    // 2048 float4 per row / 128 threads = 16 float4 per thread per tensor.
    #pragma unroll 4
    for (int i = 0; i < 16; i++) {
        float4 pv = __ldcs(&p4[gtid + i * GROUP]);
        float4 gv = __ldcs(&g4[gtid + i * GROUP]);

        #pragma unroll
        for (int k = 0; k < 4; k++) {
            float pe = (&pv.x)[k];
            float ge = (&gv.x)[k];
            float a = fmaf(pe, ge, ESP);
            float b = fmaf(1.0f - pe, 1.0f - ge, ESP);
            float l = 1.0f - (fsqrt_approx(a) + fsqrt_approx(b));
            bool nz = (ge != 0.0f);
            sum += nz ? l : 0.0f;
            cnt += nz ? 1 : 0;
        }
    }

    // Warp reduction
    #pragma unroll
    for (int o = 16; o > 0; o >>= 1) {
        sum += __shfl_down_sync(0xffffffffu, sum, o);
        cnt += __shfl_down_sync(0xffffffffu, cnt, o);
    }

    // 8 warps total; warps 0-3 belong to row half 0, warps 4-7 to half 1.
    __shared__ float s_sum[8];
    __shared__ int   s_cnt[8];
    const int wid = tid >> 5;
    const int lid = tid & 31;
    if (lid == 0) {
        s_sum[wid] = sum;
        s_cnt[wid] = cnt;
    }
    __syncthreads();

    // One thread per half finalizes its row.
    if (gtid == 0) {
        const int base = half * 4;
        float bsum = s_sum[base] + s_sum[base + 1] + s_sum[base + 2] + s_sum[base + 3];
        int   bcnt = s_cnt[base] + s_cnt[base + 1] + s_cnt[base + 2] + s_cnt[base + 3];
        float row_loss = (bcnt > 0) ? (bsum / (float)bcnt) : 0.0f;

        atomicAdd(&g_accum, (double)row_loss);
        __threadfence();
        unsigned int t = atomicAdd(&g_ticket, 1u);
        if (t == (unsigned int)(n_rows - 1)) {
            // Last row finalizer: read-and-reset state atomically so every
            // graph replay starts zeroed (matches zero-initialized first
            // call), then emit the mean.
            unsigned long long bits =
                atomicExch((unsigned long long*)&g_accum, 0ull);
            atomicExch(&g_ticket, 0u);
            double total = __longlong_as_double((long long)bits);
            out[0] = (float)(total / (double)n_rows);
        }
    }
}

extern "C" void kernel_launch(void* const* d_in, const int* in_sizes, int n_in,
                              void* d_out, int out_size) {
    const float* p = (const float*)d_in[0];
    const float* g = (const float*)d_in[1];
    float* out = (float*)d_out;

    const int total = in_sizes[0];
    const int n_rows = total / C_DIM;   // 16384

    mfl_fused_kernel<<<n_rows / ROWS_PER_BLOCK, THREADS>>>(p, g, out, n_rows);
}